// round 1
// baseline (speedup 1.0000x reference)
#include <cuda_runtime.h>
#include <math.h>

#define Bc 2
#define Sc 2048
#define Ec 1024
#define Hc 16
#define Dc 64
#define Fc 4096
#define Mc (Bc*Sc)          // 4096 rows

// ---------------- scratch (no cudaMalloc allowed) ----------------
__device__ float g_n  [Mc*Ec];
__device__ float g_q  [Mc*Ec];
__device__ float g_k  [Mc*Ec];
__device__ float g_v  [Mc*Ec];
__device__ float g_ctx[Mc*Ec];
__device__ float g_res[Mc*Ec];
__device__ float g_x2 [Mc*Ec];
__device__ float g_f1 [Mc*Fc];

// ---------------- LayerNorm: one block per row, E=1024 ----------------
__global__ void __launch_bounds__(256) ln_kernel(const float* __restrict__ x,
                                                 const float* __restrict__ g,
                                                 const float* __restrict__ b,
                                                 float* __restrict__ out) {
    int row = blockIdx.x;
    int tid = threadIdx.x;
    const float4* xr = (const float4*)(x + (size_t)row * Ec);
    float4 xv = xr[tid];
    float s  = xv.x + xv.y + xv.z + xv.w;
    float sq = xv.x*xv.x + xv.y*xv.y + xv.z*xv.z + xv.w*xv.w;
    #pragma unroll
    for (int o = 16; o; o >>= 1) {
        s  += __shfl_xor_sync(0xffffffffu, s,  o);
        sq += __shfl_xor_sync(0xffffffffu, sq, o);
    }
    __shared__ float ws[8], wq[8];
    __shared__ float s_mu, s_rstd;
    int lane = tid & 31, wid = tid >> 5;
    if (lane == 0) { ws[wid] = s; wq[wid] = sq; }
    __syncthreads();
    if (tid == 0) {
        float S = 0.f, Q = 0.f;
        #pragma unroll
        for (int i = 0; i < 8; i++) { S += ws[i]; Q += wq[i]; }
        float mu  = S * (1.0f / Ec);
        float var = Q * (1.0f / Ec) - mu * mu;
        s_mu = mu;
        s_rstd = rsqrtf(var + 1e-5f);
    }
    __syncthreads();
    float mu = s_mu, rstd = s_rstd;
    float4 gv = ((const float4*)g)[tid];
    float4 bv = ((const float4*)b)[tid];
    float4 ov;
    ov.x = (xv.x - mu) * rstd * gv.x + bv.x;
    ov.y = (xv.y - mu) * rstd * gv.y + bv.y;
    ov.z = (xv.z - mu) * rstd * gv.z + bv.z;
    ov.w = (xv.w - mu) * rstd * gv.w + bv.w;
    ((float4*)(out + (size_t)row * Ec))[tid] = ov;
}

// ---------------- tiled SGEMM, 64x64x16 tile, 256 threads, 4x4 microtile ----------------
enum { EP_PLAIN = 0, EP_HEADS = 1, EP_RES = 2, EP_GELU = 3 };

template<int EP>
__global__ void __launch_bounds__(256) sgemm(const float* __restrict__ A,
                                             const float* __restrict__ W,
                                             const float* __restrict__ bias,
                                             const float* __restrict__ res,
                                             float* __restrict__ C,
                                             int M, int N, int K) {
    __shared__ float As[16][64];
    __shared__ float Bs[16][64];
    int tid = threadIdx.x;
    int tx = tid & 15, ty = tid >> 4;
    int row0 = blockIdx.y * 64, col0 = blockIdx.x * 64;

    int am = tid >> 2;            // 0..63
    int ak = (tid & 3) * 4;       // 0,4,8,12
    int bk = tid >> 4;            // 0..15
    int bn = (tid & 15) * 4;      // 0..60

    const float* Aptr = A + (size_t)(row0 + am) * K + ak;
    const float* Wptr = W + (size_t)bk * N + col0 + bn;

    float acc[4][4];
    #pragma unroll
    for (int i = 0; i < 4; i++)
        #pragma unroll
        for (int j = 0; j < 4; j++) acc[i][j] = 0.f;

    for (int k0 = 0; k0 < K; k0 += 16) {
        float4 av = *(const float4*)(Aptr + k0);
        float4 bv = *(const float4*)(Wptr + (size_t)k0 * N);
        As[ak + 0][am] = av.x;
        As[ak + 1][am] = av.y;
        As[ak + 2][am] = av.z;
        As[ak + 3][am] = av.w;
        *(float4*)&Bs[bk][bn] = bv;
        __syncthreads();
        #pragma unroll
        for (int kk = 0; kk < 16; kk++) {
            float4 a4 = *(const float4*)&As[kk][ty * 4];
            float4 b4 = *(const float4*)&Bs[kk][tx * 4];
            float ar[4] = {a4.x, a4.y, a4.z, a4.w};
            float br[4] = {b4.x, b4.y, b4.z, b4.w};
            #pragma unroll
            for (int i = 0; i < 4; i++)
                #pragma unroll
                for (int j = 0; j < 4; j++)
                    acc[i][j] = fmaf(ar[i], br[j], acc[i][j]);
        }
        __syncthreads();
    }

    #pragma unroll
    for (int i = 0; i < 4; i++) {
        int row = row0 + ty * 4 + i;
        #pragma unroll
        for (int j = 0; j < 4; j++) {
            int col = col0 + tx * 4 + j;
            float v = acc[i][j] + bias[col];
            if (EP == EP_GELU)
                v = 0.5f * v * (1.f + erff(v * 0.70710678118654752f));
            if (EP == EP_RES)
                v += res[(size_t)row * N + col];
            if (EP == EP_HEADS) {
                int bb = row >> 11, ss = row & 2047;
                int hh = col >> 6,  dd = col & 63;
                C[(((size_t)(bb * Hc + hh)) * Sc + ss) * Dc + dd] = v;
            } else {
                C[(size_t)row * N + col] = v;
            }
        }
    }
}

// ---------------- Flash attention: 64 q-rows x 64 kv-rows tiles, online softmax ----------------
#define LDT 68
#define ATTN_SMEM ((4 * 64 * LDT + 3 * 64) * 4)

__global__ void __launch_bounds__(256) attn_kernel(const float* __restrict__ Q,
                                                   const float* __restrict__ K,
                                                   const float* __restrict__ V,
                                                   float* __restrict__ ctx) {
    extern __shared__ float sm[];
    float* Qs = sm;                    // [64][LDT]  row-major [q][d]
    float* Ks = Qs + 64 * LDT;         // [64][LDT]  TRANSPOSED [d][kv]
    float* Vs = Ks + 64 * LDT;         // [64][LDT]  row-major [kv][d]
    float* Ss = Vs + 64 * LDT;         // [64][LDT]  scores / P
    float* rowm  = Ss + 64 * LDT;      // [64]
    float* rowl  = rowm + 64;          // [64]
    float* rowsc = rowl + 64;          // [64]

    int tid = threadIdx.x;
    int tx = tid & 15, ty = tid >> 4;
    int qt = (int)gridDim.x - 1 - (int)blockIdx.x;  // heavy tiles first
    int bh = blockIdx.y;
    int q0 = qt * 64;

    const float* Qbh = Q + (size_t)bh * Sc * Dc;
    const float* Kbh = K + (size_t)bh * Sc * Dc;
    const float* Vbh = V + (size_t)bh * Sc * Dc;

    // load Q tile (coalesced)
    #pragma unroll
    for (int it = 0; it < 4; it++) {
        int idx = tid + it * 256;
        int r = idx >> 4;
        int d = (idx & 15) * 4;
        float4 f = *(const float4*)(Qbh + (size_t)(q0 + r) * Dc + d);
        *(float4*)&Qs[r * LDT + d] = f;
    }
    if (tid < 64) { rowm[tid] = -1e30f; rowl[tid] = 0.f; }

    float o[4][4];
    #pragma unroll
    for (int i = 0; i < 4; i++)
        #pragma unroll
        for (int j = 0; j < 4; j++) o[i][j] = 0.f;

    int r0 = ty * 4, c0 = tx * 4;

    for (int kt = 0; kt <= qt; kt++) {
        int k0 = kt * 64;
        __syncthreads();   // prior PV done before overwriting Ks/Vs (also covers Q load 1st iter)
        #pragma unroll
        for (int it = 0; it < 4; it++) {
            int idx = tid + it * 256;
            int r = idx >> 4;
            int d = (idx & 15) * 4;
            float4 fk = *(const float4*)(Kbh + (size_t)(k0 + r) * Dc + d);
            Ks[(d + 0) * LDT + r] = fk.x;
            Ks[(d + 1) * LDT + r] = fk.y;
            Ks[(d + 2) * LDT + r] = fk.z;
            Ks[(d + 3) * LDT + r] = fk.w;
            float4 fv = *(const float4*)(Vbh + (size_t)(k0 + r) * Dc + d);
            *(float4*)&Vs[r * LDT + d] = fv;
        }
        __syncthreads();

        // ---- S = Q K^T * 0.125 ----
        float sacc[4][4];
        #pragma unroll
        for (int i = 0; i < 4; i++)
            #pragma unroll
            for (int j = 0; j < 4; j++) sacc[i][j] = 0.f;
        #pragma unroll
        for (int d = 0; d < 64; d++) {
            float4 kf = *(const float4*)&Ks[d * LDT + c0];
            float kv[4] = {kf.x, kf.y, kf.z, kf.w};
            #pragma unroll
            for (int i = 0; i < 4; i++) {
                float qv = Qs[(r0 + i) * LDT + d];
                #pragma unroll
                for (int j = 0; j < 4; j++)
                    sacc[i][j] = fmaf(qv, kv[j], sacc[i][j]);
            }
        }
        bool diag = (kt == qt);
        #pragma unroll
        for (int i = 0; i < 4; i++) {
            #pragma unroll
            for (int j = 0; j < 4; j++) {
                float v = sacc[i][j] * 0.125f;
                if (diag && (c0 + j) > (r0 + i)) v = -1e30f;
                Ss[(r0 + i) * LDT + c0 + j] = v;
            }
        }
        __syncthreads();

        // ---- online softmax (4 lanes per row, 16 cols each) ----
        {
            int row = tid >> 2;
            int quad = tid & 3;
            float* srow = Ss + row * LDT + quad * 16;
            float vals[16];
            float mx = -1e30f;
            #pragma unroll
            for (int c = 0; c < 16; c++) { vals[c] = srow[c]; mx = fmaxf(mx, vals[c]); }
            mx = fmaxf(mx, __shfl_xor_sync(0xffffffffu, mx, 1));
            mx = fmaxf(mx, __shfl_xor_sync(0xffffffffu, mx, 2));
            float mold = rowm[row];
            float mnew = fmaxf(mold, mx);
            float lsum = 0.f;
            #pragma unroll
            for (int c = 0; c < 16; c++) {
                float e = __expf(vals[c] - mnew);
                srow[c] = e;
                lsum += e;
            }
            lsum += __shfl_xor_sync(0xffffffffu, lsum, 1);
            lsum += __shfl_xor_sync(0xffffffffu, lsum, 2);
            if (quad == 0) {
                float scale = __expf(mold - mnew);
                rowsc[row] = scale;
                rowm[row]  = mnew;
                rowl[row]  = rowl[row] * scale + lsum;
            }
        }
        __syncthreads();

        // ---- O = O*scale + P V ----
        float sc[4];
        #pragma unroll
        for (int i = 0; i < 4; i++) sc[i] = rowsc[r0 + i];
        #pragma unroll
        for (int i = 0; i < 4; i++)
            #pragma unroll
            for (int j = 0; j < 4; j++) o[i][j] *= sc[i];
        #pragma unroll
        for (int jj = 0; jj < 64; jj++) {
            float4 vf = *(const float4*)&Vs[jj * LDT + c0];
            float vv[4] = {vf.x, vf.y, vf.z, vf.w};
            #pragma unroll
            for (int i = 0; i < 4; i++) {
                float p = Ss[(r0 + i) * LDT + jj];
                #pragma unroll
                for (int j = 0; j < 4; j++)
                    o[i][j] = fmaf(p, vv[j], o[i][j]);
            }
        }
    }

    // ---- write ctx [B,S,E] ----
    int bb = bh >> 4, hh = bh & 15;
    #pragma unroll
    for (int i = 0; i < 4; i++) {
        float li = 1.f / rowl[r0 + i];
        int qi = q0 + r0 + i;
        float4 ov;
        ov.x = o[i][0] * li; ov.y = o[i][1] * li;
        ov.z = o[i][2] * li; ov.w = o[i][3] * li;
        *(float4*)(ctx + ((size_t)bb * Sc + qi) * Ec + hh * Dc + c0) = ov;
    }
}

// ---------------- launch ----------------
extern "C" void kernel_launch(void* const* d_in, const int* in_sizes, int n_in,
                              void* d_out, int out_size) {
    const float* x    = (const float*)d_in[0];
    // d_in[1] = mask (causal tril) — applied analytically
    const float* Wq   = (const float*)d_in[2];
    const float* bq   = (const float*)d_in[3];
    const float* Wk   = (const float*)d_in[4];
    const float* bk   = (const float*)d_in[5];
    const float* Wv   = (const float*)d_in[6];
    const float* bv   = (const float*)d_in[7];
    const float* Wo   = (const float*)d_in[8];
    const float* bo   = (const float*)d_in[9];
    const float* W1   = (const float*)d_in[10];
    const float* b1   = (const float*)d_in[11];
    const float* W2   = (const float*)d_in[12];
    const float* b2   = (const float*)d_in[13];
    const float* ln1g = (const float*)d_in[14];
    const float* ln1b = (const float*)d_in[15];
    const float* ln2g = (const float*)d_in[16];
    const float* ln2b = (const float*)d_in[17];
    float* out = (float*)d_out;

    float *n_, *q_, *k_, *v_, *ctx_, *res_, *x2_, *f1_;
    cudaGetSymbolAddress((void**)&n_,   g_n);
    cudaGetSymbolAddress((void**)&q_,   g_q);
    cudaGetSymbolAddress((void**)&k_,   g_k);
    cudaGetSymbolAddress((void**)&v_,   g_v);
    cudaGetSymbolAddress((void**)&ctx_, g_ctx);
    cudaGetSymbolAddress((void**)&res_, g_res);
    cudaGetSymbolAddress((void**)&x2_,  g_x2);
    cudaGetSymbolAddress((void**)&f1_,  g_f1);

    // 1. LN1
    ln_kernel<<<Mc, 256>>>(x, ln1g, ln1b, n_);

    // 2. Q/K/V projections, written directly in [B,H,S,D]
    sgemm<EP_HEADS><<<dim3(Ec/64, Mc/64), 256>>>(n_, Wq, bq, nullptr, q_, Mc, Ec, Ec);
    sgemm<EP_HEADS><<<dim3(Ec/64, Mc/64), 256>>>(n_, Wk, bk, nullptr, k_, Mc, Ec, Ec);
    sgemm<EP_HEADS><<<dim3(Ec/64, Mc/64), 256>>>(n_, Wv, bv, nullptr, v_, Mc, Ec, Ec);

    // 3. Flash attention -> ctx [B,S,E]
    cudaFuncSetAttribute(attn_kernel, cudaFuncAttributeMaxDynamicSharedMemorySize, ATTN_SMEM);
    attn_kernel<<<dim3(Sc/64, Bc*Hc), 256, ATTN_SMEM>>>(q_, k_, v_, ctx_);

    // 4. Wo projection + residual with x
    sgemm<EP_RES><<<dim3(Ec/64, Mc/64), 256>>>(ctx_, Wo, bo, x, res_, Mc, Ec, Ec);

    // 5. LN2
    ln_kernel<<<Mc, 256>>>(res_, ln2g, ln2b, x2_);

    // 6. FFN1 + exact GELU
    sgemm<EP_GELU><<<dim3(Fc/64, Mc/64), 256>>>(x2_, W1, b1, nullptr, f1_, Mc, Fc, Ec);

    // 7. FFN2 + bias + residual(x2) -> out
    sgemm<EP_RES><<<dim3(Ec/64, Mc/64), 256>>>(f1_, W2, b2, x2_, out, Mc, Ec, Fc);
}

// round 2
// speedup vs baseline: 2.2292x; 2.2292x over previous
#include <cuda_runtime.h>
#include <math.h>
#include <stdint.h>

#define Bc 2
#define Sc 2048
#define Ec 1024
#define Hc 16
#define Dc 64
#define Fc 4096
#define Mc (Bc*Sc)          // 4096 rows

// ---------------- scratch (no cudaMalloc allowed) ----------------
__device__ float g_n  [Mc*Ec];
__device__ float g_q  [Mc*Ec];
__device__ float g_k  [Mc*Ec];
__device__ float g_v  [Mc*Ec];
__device__ float g_ctx[Mc*Ec];
__device__ float g_res[Mc*Ec];
__device__ float g_x2 [Mc*Ec];
__device__ float g_f1 [Mc*Fc];

// ---------------- helpers ----------------
__device__ __forceinline__ uint32_t f2tf(float f) {
    uint32_t u;
    asm("cvt.rna.tf32.f32 %0, %1;" : "=r"(u) : "f"(f));
    return u;
}

__device__ __forceinline__ void mma8(float* c, const uint32_t* a, const uint32_t* b) {
    asm volatile(
        "mma.sync.aligned.m16n8k8.row.col.f32.tf32.tf32.f32 "
        "{%0,%1,%2,%3}, {%4,%5,%6,%7}, {%8,%9}, {%0,%1,%2,%3};\n"
        : "+f"(c[0]), "+f"(c[1]), "+f"(c[2]), "+f"(c[3])
        : "r"(a[0]), "r"(a[1]), "r"(a[2]), "r"(a[3]),
          "r"(b[0]), "r"(b[1]));
}

// ---------------- LayerNorm: one block per row, E=1024 ----------------
__global__ void __launch_bounds__(256) ln_kernel(const float* __restrict__ x,
                                                 const float* __restrict__ g,
                                                 const float* __restrict__ b,
                                                 float* __restrict__ out) {
    int row = blockIdx.x;
    int tid = threadIdx.x;
    const float4* xr = (const float4*)(x + (size_t)row * Ec);
    float4 xv = xr[tid];
    float s  = xv.x + xv.y + xv.z + xv.w;
    float sq = xv.x*xv.x + xv.y*xv.y + xv.z*xv.z + xv.w*xv.w;
    #pragma unroll
    for (int o = 16; o; o >>= 1) {
        s  += __shfl_xor_sync(0xffffffffu, s,  o);
        sq += __shfl_xor_sync(0xffffffffu, sq, o);
    }
    __shared__ float ws[8], wq[8];
    __shared__ float s_mu, s_rstd;
    int lane = tid & 31, wid = tid >> 5;
    if (lane == 0) { ws[wid] = s; wq[wid] = sq; }
    __syncthreads();
    if (tid == 0) {
        float S = 0.f, Q = 0.f;
        #pragma unroll
        for (int i = 0; i < 8; i++) { S += ws[i]; Q += wq[i]; }
        float mu  = S * (1.0f / Ec);
        float var = Q * (1.0f / Ec) - mu * mu;
        s_mu = mu;
        s_rstd = rsqrtf(var + 1e-5f);
    }
    __syncthreads();
    float mu = s_mu, rstd = s_rstd;
    float4 gv = ((const float4*)g)[tid];
    float4 bv = ((const float4*)b)[tid];
    float4 ov;
    ov.x = (xv.x - mu) * rstd * gv.x + bv.x;
    ov.y = (xv.y - mu) * rstd * gv.y + bv.y;
    ov.z = (xv.z - mu) * rstd * gv.z + bv.z;
    ov.w = (xv.w - mu) * rstd * gv.w + bv.w;
    ((float4*)(out + (size_t)row * Ec))[tid] = ov;
}

// ---------------- tf32 tensor-core GEMM: 128x128x32, 8 warps ----------------
enum { EP_PLAIN = 0, EP_HEADS = 1, EP_RES = 2, EP_GELU = 3 };

#define BM 128
#define BN 128
#define BK 32
#define LDA 36    // As stride (floats): bank = (4m + c) % 32, conflict-free frags
#define LDB 136   // Bs stride (floats): bank = (8c + n) % 32, conflict-free frags

template<int EP>
__global__ void __launch_bounds__(256, 1) tgemm(const float* __restrict__ A,
                                                const float* __restrict__ W,
                                                const float* __restrict__ bias,
                                                const float* __restrict__ res,
                                                float* __restrict__ C,
                                                int M, int N, int K) {
    __shared__ uint32_t As[BM * LDA];
    __shared__ uint32_t Bs[BK * LDB];

    int tid  = threadIdx.x;
    int lane = tid & 31;
    int w    = tid >> 5;
    int wm   = (w & 3) * 32;   // warp row offset in tile (4 warps along M)
    int wn   = (w >> 2) * 64;  // warp col offset in tile (2 warps along N)
    int row0 = blockIdx.y * BM;
    int col0 = blockIdx.x * BN;

    const float* Ab = A + (size_t)row0 * K;
    const float* Wb = W + col0;

    float4 pa[4], pb[4];
    // prefetch first k-tile
    #pragma unroll
    for (int i = 0; i < 4; i++) {
        int idx = tid + i * 256;
        int r  = idx >> 3, kc = (idx & 7) * 4;
        pa[i] = *(const float4*)(Ab + (size_t)r * K + kc);
        int kr = idx >> 5, nc = (idx & 31) * 4;
        pb[i] = *(const float4*)(Wb + (size_t)kr * N + nc);
    }

    float acc[2][8][4];
    #pragma unroll
    for (int mi = 0; mi < 2; mi++)
        #pragma unroll
        for (int ni = 0; ni < 8; ni++)
            #pragma unroll
            for (int q = 0; q < 4; q++) acc[mi][ni][q] = 0.f;

    int nk = K / BK;
    for (int kt = 0; kt < nk; kt++) {
        // fill smem (with tf32 rounding)
        #pragma unroll
        for (int i = 0; i < 4; i++) {
            int idx = tid + i * 256;
            int r  = idx >> 3, kc = (idx & 7) * 4;
            As[r * LDA + kc + 0] = f2tf(pa[i].x);
            As[r * LDA + kc + 1] = f2tf(pa[i].y);
            As[r * LDA + kc + 2] = f2tf(pa[i].z);
            As[r * LDA + kc + 3] = f2tf(pa[i].w);
            int kr = idx >> 5, nc = (idx & 31) * 4;
            Bs[kr * LDB + nc + 0] = f2tf(pb[i].x);
            Bs[kr * LDB + nc + 1] = f2tf(pb[i].y);
            Bs[kr * LDB + nc + 2] = f2tf(pb[i].z);
            Bs[kr * LDB + nc + 3] = f2tf(pb[i].w);
        }
        __syncthreads();

        // prefetch next k-tile
        if (kt + 1 < nk) {
            int k0 = (kt + 1) * BK;
            #pragma unroll
            for (int i = 0; i < 4; i++) {
                int idx = tid + i * 256;
                int r  = idx >> 3, kc = (idx & 7) * 4;
                pa[i] = *(const float4*)(Ab + (size_t)r * K + k0 + kc);
                int kr = idx >> 5, nc = (idx & 31) * 4;
                pb[i] = *(const float4*)(Wb + (size_t)(k0 + kr) * N + nc);
            }
        }

        int r_ = lane >> 2, c_ = lane & 3;
        #pragma unroll
        for (int ks = 0; ks < 4; ks++) {
            int kb = ks * 8;
            uint32_t af[2][4], bf[8][2];
            #pragma unroll
            for (int mi = 0; mi < 2; mi++) {
                int m = wm + mi * 16 + r_;
                af[mi][0] = As[m * LDA + kb + c_];
                af[mi][1] = As[(m + 8) * LDA + kb + c_];
                af[mi][2] = As[m * LDA + kb + c_ + 4];
                af[mi][3] = As[(m + 8) * LDA + kb + c_ + 4];
            }
            #pragma unroll
            for (int ni = 0; ni < 8; ni++) {
                int n = wn + ni * 8 + r_;
                bf[ni][0] = Bs[(kb + c_) * LDB + n];
                bf[ni][1] = Bs[(kb + c_ + 4) * LDB + n];
            }
            #pragma unroll
            for (int mi = 0; mi < 2; mi++)
                #pragma unroll
                for (int ni = 0; ni < 8; ni++)
                    mma8(acc[mi][ni], af[mi], bf[ni]);
        }
        __syncthreads();
    }

    // ---- epilogue ----
    int r_ = lane >> 2, c2 = (lane & 3) * 2;
    #pragma unroll
    for (int mi = 0; mi < 2; mi++) {
        #pragma unroll
        for (int ni = 0; ni < 8; ni++) {
            #pragma unroll
            for (int h = 0; h < 2; h++) {
                int row = row0 + wm + mi * 16 + r_ + h * 8;
                int col = col0 + wn + ni * 8 + c2;
                float v0 = acc[mi][ni][h * 2 + 0] + bias[col];
                float v1 = acc[mi][ni][h * 2 + 1] + bias[col + 1];
                if (EP == EP_GELU) {
                    v0 = 0.5f * v0 * (1.f + erff(v0 * 0.70710678118654752f));
                    v1 = 0.5f * v1 * (1.f + erff(v1 * 0.70710678118654752f));
                }
                if (EP == EP_RES) {
                    v0 += res[(size_t)row * N + col];
                    v1 += res[(size_t)row * N + col + 1];
                }
                if (EP == EP_HEADS) {
                    int bb = row >> 11, ss = row & 2047;
                    int hh = col >> 6,  dd = col & 63;
                    *(float2*)&C[(((size_t)(bb * Hc + hh)) * Sc + ss) * Dc + dd] =
                        make_float2(v0, v1);
                } else {
                    *(float2*)&C[(size_t)row * N + col] = make_float2(v0, v1);
                }
            }
        }
    }
}

// ---------------- Flash attention: 64x64 tiles, online softmax (fp32 SIMT) ----------------
#define LDT 68
#define ATTN_SMEM ((4 * 64 * LDT + 3 * 64) * 4)

__global__ void __launch_bounds__(256) attn_kernel(const float* __restrict__ Q,
                                                   const float* __restrict__ K,
                                                   const float* __restrict__ V,
                                                   float* __restrict__ ctx) {
    extern __shared__ float sm[];
    float* Qs = sm;                    // [64][LDT]  row-major [q][d]
    float* Ks = Qs + 64 * LDT;         // [64][LDT]  TRANSPOSED [d][kv]
    float* Vs = Ks + 64 * LDT;         // [64][LDT]  row-major [kv][d]
    float* Ss = Vs + 64 * LDT;         // [64][LDT]  scores / P
    float* rowm  = Ss + 64 * LDT;      // [64]
    float* rowl  = rowm + 64;          // [64]
    float* rowsc = rowl + 64;          // [64]

    int tid = threadIdx.x;
    int tx = tid & 15, ty = tid >> 4;
    int qt = (int)gridDim.x - 1 - (int)blockIdx.x;  // heavy tiles first
    int bh = blockIdx.y;
    int q0 = qt * 64;

    const float* Qbh = Q + (size_t)bh * Sc * Dc;
    const float* Kbh = K + (size_t)bh * Sc * Dc;
    const float* Vbh = V + (size_t)bh * Sc * Dc;

    #pragma unroll
    for (int it = 0; it < 4; it++) {
        int idx = tid + it * 256;
        int r = idx >> 4;
        int d = (idx & 15) * 4;
        float4 f = *(const float4*)(Qbh + (size_t)(q0 + r) * Dc + d);
        *(float4*)&Qs[r * LDT + d] = f;
    }
    if (tid < 64) { rowm[tid] = -1e30f; rowl[tid] = 0.f; }

    float o[4][4];
    #pragma unroll
    for (int i = 0; i < 4; i++)
        #pragma unroll
        for (int j = 0; j < 4; j++) o[i][j] = 0.f;

    int r0 = ty * 4, c0 = tx * 4;

    for (int kt = 0; kt <= qt; kt++) {
        int k0 = kt * 64;
        __syncthreads();
        #pragma unroll
        for (int it = 0; it < 4; it++) {
            int idx = tid + it * 256;
            int r = idx >> 4;
            int d = (idx & 15) * 4;
            float4 fk = *(const float4*)(Kbh + (size_t)(k0 + r) * Dc + d);
            Ks[(d + 0) * LDT + r] = fk.x;
            Ks[(d + 1) * LDT + r] = fk.y;
            Ks[(d + 2) * LDT + r] = fk.z;
            Ks[(d + 3) * LDT + r] = fk.w;
            float4 fv = *(const float4*)(Vbh + (size_t)(k0 + r) * Dc + d);
            *(float4*)&Vs[r * LDT + d] = fv;
        }
        __syncthreads();

        float sacc[4][4];
        #pragma unroll
        for (int i = 0; i < 4; i++)
            #pragma unroll
            for (int j = 0; j < 4; j++) sacc[i][j] = 0.f;
        #pragma unroll
        for (int d = 0; d < 64; d++) {
            float4 kf = *(const float4*)&Ks[d * LDT + c0];
            float kv[4] = {kf.x, kf.y, kf.z, kf.w};
            #pragma unroll
            for (int i = 0; i < 4; i++) {
                float qv = Qs[(r0 + i) * LDT + d];
                #pragma unroll
                for (int j = 0; j < 4; j++)
                    sacc[i][j] = fmaf(qv, kv[j], sacc[i][j]);
            }
        }
        bool diag = (kt == qt);
        #pragma unroll
        for (int i = 0; i < 4; i++) {
            #pragma unroll
            for (int j = 0; j < 4; j++) {
                float v = sacc[i][j] * 0.125f;
                if (diag && (c0 + j) > (r0 + i)) v = -1e30f;
                Ss[(r0 + i) * LDT + c0 + j] = v;
            }
        }
        __syncthreads();

        {
            int row = tid >> 2;
            int quad = tid & 3;
            float* srow = Ss + row * LDT + quad * 16;
            float vals[16];
            float mx = -1e30f;
            #pragma unroll
            for (int c = 0; c < 16; c++) { vals[c] = srow[c]; mx = fmaxf(mx, vals[c]); }
            mx = fmaxf(mx, __shfl_xor_sync(0xffffffffu, mx, 1));
            mx = fmaxf(mx, __shfl_xor_sync(0xffffffffu, mx, 2));
            float mold = rowm[row];
            float mnew = fmaxf(mold, mx);
            float lsum = 0.f;
            #pragma unroll
            for (int c = 0; c < 16; c++) {
                float e = __expf(vals[c] - mnew);
                srow[c] = e;
                lsum += e;
            }
            lsum += __shfl_xor_sync(0xffffffffu, lsum, 1);
            lsum += __shfl_xor_sync(0xffffffffu, lsum, 2);
            if (quad == 0) {
                float scale = __expf(mold - mnew);
                rowsc[row] = scale;
                rowm[row]  = mnew;
                rowl[row]  = rowl[row] * scale + lsum;
            }
        }
        __syncthreads();

        float sc[4];
        #pragma unroll
        for (int i = 0; i < 4; i++) sc[i] = rowsc[r0 + i];
        #pragma unroll
        for (int i = 0; i < 4; i++)
            #pragma unroll
            for (int j = 0; j < 4; j++) o[i][j] *= sc[i];
        #pragma unroll
        for (int jj = 0; jj < 64; jj++) {
            float4 vf = *(const float4*)&Vs[jj * LDT + c0];
            float vv[4] = {vf.x, vf.y, vf.z, vf.w};
            #pragma unroll
            for (int i = 0; i < 4; i++) {
                float p = Ss[(r0 + i) * LDT + jj];
                #pragma unroll
                for (int j = 0; j < 4; j++)
                    o[i][j] = fmaf(p, vv[j], o[i][j]);
            }
        }
    }

    int bb = bh >> 4, hh = bh & 15;
    #pragma unroll
    for (int i = 0; i < 4; i++) {
        float li = 1.f / rowl[r0 + i];
        int qi = q0 + r0 + i;
        float4 ov;
        ov.x = o[i][0] * li; ov.y = o[i][1] * li;
        ov.z = o[i][2] * li; ov.w = o[i][3] * li;
        *(float4*)(ctx + ((size_t)bb * Sc + qi) * Ec + hh * Dc + c0) = ov;
    }
}

// ---------------- launch ----------------
extern "C" void kernel_launch(void* const* d_in, const int* in_sizes, int n_in,
                              void* d_out, int out_size) {
    const float* x    = (const float*)d_in[0];
    // d_in[1] = mask (causal tril) — applied analytically
    const float* Wq   = (const float*)d_in[2];
    const float* bq   = (const float*)d_in[3];
    const float* Wk   = (const float*)d_in[4];
    const float* bk   = (const float*)d_in[5];
    const float* Wv   = (const float*)d_in[6];
    const float* bv   = (const float*)d_in[7];
    const float* Wo   = (const float*)d_in[8];
    const float* bo   = (const float*)d_in[9];
    const float* W1   = (const float*)d_in[10];
    const float* b1   = (const float*)d_in[11];
    const float* W2   = (const float*)d_in[12];
    const float* b2   = (const float*)d_in[13];
    const float* ln1g = (const float*)d_in[14];
    const float* ln1b = (const float*)d_in[15];
    const float* ln2g = (const float*)d_in[16];
    const float* ln2b = (const float*)d_in[17];
    float* out = (float*)d_out;

    float *n_, *q_, *k_, *v_, *ctx_, *res_, *x2_, *f1_;
    cudaGetSymbolAddress((void**)&n_,   g_n);
    cudaGetSymbolAddress((void**)&q_,   g_q);
    cudaGetSymbolAddress((void**)&k_,   g_k);
    cudaGetSymbolAddress((void**)&v_,   g_v);
    cudaGetSymbolAddress((void**)&ctx_, g_ctx);
    cudaGetSymbolAddress((void**)&res_, g_res);
    cudaGetSymbolAddress((void**)&x2_,  g_x2);
    cudaGetSymbolAddress((void**)&f1_,  g_f1);

    // 1. LN1
    ln_kernel<<<Mc, 256>>>(x, ln1g, ln1b, n_);

    // 2. Q/K/V projections (tf32 TC), written directly in [B,H,S,D]
    tgemm<EP_HEADS><<<dim3(Ec/BN, Mc/BM), 256>>>(n_, Wq, bq, nullptr, q_, Mc, Ec, Ec);
    tgemm<EP_HEADS><<<dim3(Ec/BN, Mc/BM), 256>>>(n_, Wk, bk, nullptr, k_, Mc, Ec, Ec);
    tgemm<EP_HEADS><<<dim3(Ec/BN, Mc/BM), 256>>>(n_, Wv, bv, nullptr, v_, Mc, Ec, Ec);

    // 3. Flash attention -> ctx [B,S,E]
    cudaFuncSetAttribute(attn_kernel, cudaFuncAttributeMaxDynamicSharedMemorySize, ATTN_SMEM);
    attn_kernel<<<dim3(Sc/64, Bc*Hc), 256, ATTN_SMEM>>>(q_, k_, v_, ctx_);

    // 4. Wo projection + residual with x
    tgemm<EP_RES><<<dim3(Ec/BN, Mc/BM), 256>>>(ctx_, Wo, bo, x, res_, Mc, Ec, Ec);

    // 5. LN2
    ln_kernel<<<Mc, 256>>>(res_, ln2g, ln2b, x2_);

    // 6. FFN1 + exact GELU
    tgemm<EP_GELU><<<dim3(Fc/BN, Mc/BM), 256>>>(x2_, W1, b1, nullptr, f1_, Mc, Fc, Ec);

    // 7. FFN2 + bias + residual(x2) -> out
    tgemm<EP_RES><<<dim3(Ec/BN, Mc/BM), 256>>>(f1_, W2, b2, x2_, out, Mc, Ec, Fc);
}

// round 3
// speedup vs baseline: 3.0953x; 1.3885x over previous
#include <cuda_runtime.h>
#include <math.h>
#include <stdint.h>

#define Bc 2
#define Sc 2048
#define Ec 1024
#define Hc 16
#define Dc 64
#define Fc 4096
#define Mc (Bc*Sc)          // 4096 rows

// ---------------- scratch (no cudaMalloc allowed) ----------------
__device__ float g_n  [Mc*Ec];
__device__ float g_q  [Mc*Ec];
__device__ float g_k  [Mc*Ec];
__device__ float g_v  [Mc*Ec];
__device__ float g_ctx[Mc*Ec];
__device__ float g_res[Mc*Ec];
__device__ float g_x2 [Mc*Ec];
__device__ float g_f1 [Mc*Fc];

// ---------------- helpers ----------------
__device__ __forceinline__ uint32_t f2tf(float f) {
    uint32_t u;
    asm("cvt.rna.tf32.f32 %0, %1;" : "=r"(u) : "f"(f));
    return u;
}

__device__ __forceinline__ void mma8(float* c, const uint32_t* a, const uint32_t* b) {
    asm volatile(
        "mma.sync.aligned.m16n8k8.row.col.f32.tf32.tf32.f32 "
        "{%0,%1,%2,%3}, {%4,%5,%6,%7}, {%8,%9}, {%0,%1,%2,%3};\n"
        : "+f"(c[0]), "+f"(c[1]), "+f"(c[2]), "+f"(c[3])
        : "r"(a[0]), "r"(a[1]), "r"(a[2]), "r"(a[3]),
          "r"(b[0]), "r"(b[1]));
}

// ---------------- LayerNorm ----------------
__global__ void __launch_bounds__(256) ln_kernel(const float* __restrict__ x,
                                                 const float* __restrict__ g,
                                                 const float* __restrict__ b,
                                                 float* __restrict__ out) {
    int row = blockIdx.x;
    int tid = threadIdx.x;
    const float4* xr = (const float4*)(x + (size_t)row * Ec);
    float4 xv = xr[tid];
    float s  = xv.x + xv.y + xv.z + xv.w;
    float sq = xv.x*xv.x + xv.y*xv.y + xv.z*xv.z + xv.w*xv.w;
    #pragma unroll
    for (int o = 16; o; o >>= 1) {
        s  += __shfl_xor_sync(0xffffffffu, s,  o);
        sq += __shfl_xor_sync(0xffffffffu, sq, o);
    }
    __shared__ float ws[8], wq[8];
    __shared__ float s_mu, s_rstd;
    int lane = tid & 31, wid = tid >> 5;
    if (lane == 0) { ws[wid] = s; wq[wid] = sq; }
    __syncthreads();
    if (tid == 0) {
        float S = 0.f, Q = 0.f;
        #pragma unroll
        for (int i = 0; i < 8; i++) { S += ws[i]; Q += wq[i]; }
        float mu  = S * (1.0f / Ec);
        float var = Q * (1.0f / Ec) - mu * mu;
        s_mu = mu;
        s_rstd = rsqrtf(var + 1e-5f);
    }
    __syncthreads();
    float mu = s_mu, rstd = s_rstd;
    float4 gv = ((const float4*)g)[tid];
    float4 bv = ((const float4*)b)[tid];
    float4 ov;
    ov.x = (xv.x - mu) * rstd * gv.x + bv.x;
    ov.y = (xv.y - mu) * rstd * gv.y + bv.y;
    ov.z = (xv.z - mu) * rstd * gv.z + bv.z;
    ov.w = (xv.w - mu) * rstd * gv.w + bv.w;
    ((float4*)(out + (size_t)row * Ec))[tid] = ov;
}

// ---------------- tf32 tensor-core GEMM: 128x128x32, 8 warps ----------------
enum { EP_PLAIN = 0, EP_HEADS = 1, EP_RES = 2, EP_GELU = 3 };

#define BM 128
#define BN 128
#define BK 32
#define LDA 36
#define LDB 136

template<int EP>
__global__ void __launch_bounds__(256, 1) tgemm(const float* __restrict__ A,
                                                const float* __restrict__ W,
                                                const float* __restrict__ bias,
                                                const float* __restrict__ res,
                                                float* __restrict__ C,
                                                int M, int N, int K) {
    __shared__ uint32_t As[BM * LDA];
    __shared__ uint32_t Bs[BK * LDB];

    int tid  = threadIdx.x;
    int lane = tid & 31;
    int w    = tid >> 5;
    int wm   = (w & 3) * 32;
    int wn   = (w >> 2) * 64;
    int row0 = blockIdx.y * BM;
    int col0 = blockIdx.x * BN;

    const float* Ab = A + (size_t)row0 * K;
    const float* Wb = W + col0;

    float4 pa[4], pb[4];
    #pragma unroll
    for (int i = 0; i < 4; i++) {
        int idx = tid + i * 256;
        int r  = idx >> 3, kc = (idx & 7) * 4;
        pa[i] = *(const float4*)(Ab + (size_t)r * K + kc);
        int kr = idx >> 5, nc = (idx & 31) * 4;
        pb[i] = *(const float4*)(Wb + (size_t)kr * N + nc);
    }

    float acc[2][8][4];
    #pragma unroll
    for (int mi = 0; mi < 2; mi++)
        #pragma unroll
        for (int ni = 0; ni < 8; ni++)
            #pragma unroll
            for (int q = 0; q < 4; q++) acc[mi][ni][q] = 0.f;

    int nk = K / BK;
    for (int kt = 0; kt < nk; kt++) {
        #pragma unroll
        for (int i = 0; i < 4; i++) {
            int idx = tid + i * 256;
            int r  = idx >> 3, kc = (idx & 7) * 4;
            As[r * LDA + kc + 0] = f2tf(pa[i].x);
            As[r * LDA + kc + 1] = f2tf(pa[i].y);
            As[r * LDA + kc + 2] = f2tf(pa[i].z);
            As[r * LDA + kc + 3] = f2tf(pa[i].w);
            int kr = idx >> 5, nc = (idx & 31) * 4;
            Bs[kr * LDB + nc + 0] = f2tf(pb[i].x);
            Bs[kr * LDB + nc + 1] = f2tf(pb[i].y);
            Bs[kr * LDB + nc + 2] = f2tf(pb[i].z);
            Bs[kr * LDB + nc + 3] = f2tf(pb[i].w);
        }
        __syncthreads();

        if (kt + 1 < nk) {
            int k0 = (kt + 1) * BK;
            #pragma unroll
            for (int i = 0; i < 4; i++) {
                int idx = tid + i * 256;
                int r  = idx >> 3, kc = (idx & 7) * 4;
                pa[i] = *(const float4*)(Ab + (size_t)r * K + k0 + kc);
                int kr = idx >> 5, nc = (idx & 31) * 4;
                pb[i] = *(const float4*)(Wb + (size_t)(k0 + kr) * N + nc);
            }
        }

        int r_ = lane >> 2, c_ = lane & 3;
        #pragma unroll
        for (int ks = 0; ks < 4; ks++) {
            int kb = ks * 8;
            uint32_t af[2][4], bf[8][2];
            #pragma unroll
            for (int mi = 0; mi < 2; mi++) {
                int m = wm + mi * 16 + r_;
                af[mi][0] = As[m * LDA + kb + c_];
                af[mi][1] = As[(m + 8) * LDA + kb + c_];
                af[mi][2] = As[m * LDA + kb + c_ + 4];
                af[mi][3] = As[(m + 8) * LDA + kb + c_ + 4];
            }
            #pragma unroll
            for (int ni = 0; ni < 8; ni++) {
                int n = wn + ni * 8 + r_;
                bf[ni][0] = Bs[(kb + c_) * LDB + n];
                bf[ni][1] = Bs[(kb + c_ + 4) * LDB + n];
            }
            #pragma unroll
            for (int mi = 0; mi < 2; mi++)
                #pragma unroll
                for (int ni = 0; ni < 8; ni++)
                    mma8(acc[mi][ni], af[mi], bf[ni]);
        }
        __syncthreads();
    }

    int r_ = lane >> 2, c2 = (lane & 3) * 2;
    #pragma unroll
    for (int mi = 0; mi < 2; mi++) {
        #pragma unroll
        for (int ni = 0; ni < 8; ni++) {
            #pragma unroll
            for (int h = 0; h < 2; h++) {
                int row = row0 + wm + mi * 16 + r_ + h * 8;
                int col = col0 + wn + ni * 8 + c2;
                float v0 = acc[mi][ni][h * 2 + 0] + bias[col];
                float v1 = acc[mi][ni][h * 2 + 1] + bias[col + 1];
                if (EP == EP_GELU) {
                    v0 = 0.5f * v0 * (1.f + erff(v0 * 0.70710678118654752f));
                    v1 = 0.5f * v1 * (1.f + erff(v1 * 0.70710678118654752f));
                }
                if (EP == EP_RES) {
                    v0 += res[(size_t)row * N + col];
                    v1 += res[(size_t)row * N + col + 1];
                }
                if (EP == EP_HEADS) {
                    int bb = row >> 11, ss = row & 2047;
                    int hh = col >> 6,  dd = col & 63;
                    *(float2*)&C[(((size_t)(bb * Hc + hh)) * Sc + ss) * Dc + dd] =
                        make_float2(v0, v1);
                } else {
                    *(float2*)&C[(size_t)row * N + col] = make_float2(v0, v1);
                }
            }
        }
    }
}

// ---------------- tf32 tensor-core flash attention ----------------
// 64 q-rows x 64 kv tiles, 4 warps (16 q-rows each), online softmax in C-frag regs.
#define LDK 68   // bank = 4r + c  (conflict-free B-frag loads)
#define LDV 72   // bank = 8c + r  (conflict-free B-frag loads)
#define LDP 68
#define ATTN_SMEM ((64*LDK + 64*LDV + 64*LDP) * 4)

__global__ void __launch_bounds__(128) attn_tc(const float* __restrict__ Q,
                                               const float* __restrict__ K,
                                               const float* __restrict__ V,
                                               float* __restrict__ ctx) {
    extern __shared__ uint32_t smu[];
    uint32_t* Ks = smu;                 // [64][LDK] tf32 bits, row-major [kv][d]
    uint32_t* Vs = Ks + 64 * LDK;       // [64][LDV] tf32 bits, row-major [kv][d]
    uint32_t* Ps = Vs + 64 * LDV;       // [64][LDP] warp-private P stripes / Q staging

    int tid = threadIdx.x, lane = tid & 31, w = tid >> 5;
    int r_ = lane >> 2, c_ = lane & 3;
    int qt = (int)gridDim.x - 1 - (int)blockIdx.x;  // heavy tiles first
    int bh = blockIdx.y;
    int q0 = qt * 64;

    const float* Qb = Q + (size_t)bh * Sc * Dc;
    const float* Kb = K + (size_t)bh * Sc * Dc;
    const float* Vb = V + (size_t)bh * Sc * Dc;

    // ---- stage Q (pre-scaled) into Ps, then load per-warp A-frags into regs ----
    #pragma unroll
    for (int it = 0; it < 8; it++) {
        int idx = tid + it * 128;
        int r = idx >> 4, d4 = (idx & 15) * 4;
        float4 f = *(const float4*)(Qb + (size_t)(q0 + r) * Dc + d4);
        float* dst = (float*)&Ps[r * LDP + d4];
        dst[0] = f.x * 0.125f; dst[1] = f.y * 0.125f;
        dst[2] = f.z * 0.125f; dst[3] = f.w * 0.125f;
    }
    __syncthreads();
    uint32_t qf[8][4];
    {
        const float* pw = (const float*)(Ps + w * 16 * LDP);
        #pragma unroll
        for (int kc = 0; kc < 8; kc++) {
            int kb = kc * 8;
            qf[kc][0] = f2tf(pw[r_ * LDP + kb + c_]);
            qf[kc][1] = f2tf(pw[(r_ + 8) * LDP + kb + c_]);
            qf[kc][2] = f2tf(pw[r_ * LDP + kb + c_ + 4]);
            qf[kc][3] = f2tf(pw[(r_ + 8) * LDP + kb + c_ + 4]);
        }
    }

    float o[8][4];
    #pragma unroll
    for (int nf = 0; nf < 8; nf++)
        #pragma unroll
        for (int q = 0; q < 4; q++) o[nf][q] = 0.f;
    float m0 = -1e30f, m1 = -1e30f, l0 = 0.f, l1 = 0.f;

    uint32_t* pw = Ps + w * 16 * LDP;

    for (int kt = 0; kt <= qt; kt++) {
        int k0 = kt * 64;
        __syncthreads();   // Vs/Ks consumed by previous PV before overwrite
        #pragma unroll
        for (int it = 0; it < 8; it++) {
            int idx = tid + it * 128;
            int r = idx >> 4, d4 = (idx & 15) * 4;
            float4 fk = *(const float4*)(Kb + (size_t)(k0 + r) * Dc + d4);
            Ks[r * LDK + d4 + 0] = f2tf(fk.x);
            Ks[r * LDK + d4 + 1] = f2tf(fk.y);
            Ks[r * LDK + d4 + 2] = f2tf(fk.z);
            Ks[r * LDK + d4 + 3] = f2tf(fk.w);
            float4 fv = *(const float4*)(Vb + (size_t)(k0 + r) * Dc + d4);
            Vs[r * LDV + d4 + 0] = f2tf(fv.x);
            Vs[r * LDV + d4 + 1] = f2tf(fv.y);
            Vs[r * LDV + d4 + 2] = f2tf(fv.z);
            Vs[r * LDV + d4 + 3] = f2tf(fv.w);
        }
        __syncthreads();

        // ---- S = (Q/8) K^T ----
        float sacc[8][4];
        #pragma unroll
        for (int nf = 0; nf < 8; nf++)
            #pragma unroll
            for (int q = 0; q < 4; q++) sacc[nf][q] = 0.f;
        #pragma unroll
        for (int kc = 0; kc < 8; kc++) {
            int kb = kc * 8;
            #pragma unroll
            for (int nf = 0; nf < 8; nf++) {
                uint32_t b[2];
                b[0] = Ks[(nf * 8 + r_) * LDK + kb + c_];
                b[1] = Ks[(nf * 8 + r_) * LDK + kb + c_ + 4];
                mma8(sacc[nf], qf[kc], b);
            }
        }

        // ---- causal mask on the diagonal tile (tile-relative coords) ----
        if (kt == qt) {
            int rr = w * 16 + r_;
            #pragma unroll
            for (int nf = 0; nf < 8; nf++) {
                int cb = nf * 8 + 2 * c_;
                if (cb     > rr)     sacc[nf][0] = -1e30f;
                if (cb + 1 > rr)     sacc[nf][1] = -1e30f;
                if (cb     > rr + 8) sacc[nf][2] = -1e30f;
                if (cb + 1 > rr + 8) sacc[nf][3] = -1e30f;
            }
        }

        // ---- online softmax (register C-frag layout, quad reductions) ----
        float mx0 = -1e30f, mx1 = -1e30f;
        #pragma unroll
        for (int nf = 0; nf < 8; nf++) {
            mx0 = fmaxf(mx0, fmaxf(sacc[nf][0], sacc[nf][1]));
            mx1 = fmaxf(mx1, fmaxf(sacc[nf][2], sacc[nf][3]));
        }
        mx0 = fmaxf(mx0, __shfl_xor_sync(0xffffffffu, mx0, 1));
        mx0 = fmaxf(mx0, __shfl_xor_sync(0xffffffffu, mx0, 2));
        mx1 = fmaxf(mx1, __shfl_xor_sync(0xffffffffu, mx1, 1));
        mx1 = fmaxf(mx1, __shfl_xor_sync(0xffffffffu, mx1, 2));
        float mn0 = fmaxf(m0, mx0), mn1 = fmaxf(m1, mx1);
        float es0 = __expf(m0 - mn0), es1 = __expf(m1 - mn1);
        m0 = mn0; m1 = mn1;
        float ls0 = 0.f, ls1 = 0.f;
        #pragma unroll
        for (int nf = 0; nf < 8; nf++) {
            sacc[nf][0] = __expf(sacc[nf][0] - mn0);
            sacc[nf][1] = __expf(sacc[nf][1] - mn0);
            sacc[nf][2] = __expf(sacc[nf][2] - mn1);
            sacc[nf][3] = __expf(sacc[nf][3] - mn1);
            ls0 += sacc[nf][0] + sacc[nf][1];
            ls1 += sacc[nf][2] + sacc[nf][3];
        }
        ls0 += __shfl_xor_sync(0xffffffffu, ls0, 1);
        ls0 += __shfl_xor_sync(0xffffffffu, ls0, 2);
        ls1 += __shfl_xor_sync(0xffffffffu, ls1, 1);
        ls1 += __shfl_xor_sync(0xffffffffu, ls1, 2);
        l0 = l0 * es0 + ls0;
        l1 = l1 * es1 + ls1;
        #pragma unroll
        for (int nf = 0; nf < 8; nf++) {
            o[nf][0] *= es0; o[nf][1] *= es0;
            o[nf][2] *= es1; o[nf][3] *= es1;
        }

        // ---- P to warp-private smem (tf32), re-shape C-frag -> A-frag ----
        #pragma unroll
        for (int nf = 0; nf < 8; nf++) {
            int cb = nf * 8 + 2 * c_;
            pw[r_ * LDP + cb]           = f2tf(sacc[nf][0]);
            pw[r_ * LDP + cb + 1]       = f2tf(sacc[nf][1]);
            pw[(r_ + 8) * LDP + cb]     = f2tf(sacc[nf][2]);
            pw[(r_ + 8) * LDP + cb + 1] = f2tf(sacc[nf][3]);
        }
        __syncwarp();

        // ---- O += P V ----
        #pragma unroll
        for (int kc = 0; kc < 8; kc++) {
            int kb = kc * 8;
            uint32_t af[4];
            af[0] = pw[r_ * LDP + kb + c_];
            af[1] = pw[(r_ + 8) * LDP + kb + c_];
            af[2] = pw[r_ * LDP + kb + c_ + 4];
            af[3] = pw[(r_ + 8) * LDP + kb + c_ + 4];
            #pragma unroll
            for (int nf = 0; nf < 8; nf++) {
                uint32_t b[2];
                b[0] = Vs[(kb + c_) * LDV + nf * 8 + r_];
                b[1] = Vs[(kb + c_ + 4) * LDV + nf * 8 + r_];
                mma8(o[nf], af, b);
            }
        }
        __syncwarp();
    }

    // ---- write ctx [B,S,E] ----
    int bb = bh >> 4, hh = bh & 15;
    int row0 = q0 + w * 16 + r_;
    float il0 = 1.f / l0, il1 = 1.f / l1;
    #pragma unroll
    for (int nf = 0; nf < 8; nf++) {
        int col = hh * 64 + nf * 8 + 2 * c_;
        *(float2*)&ctx[((size_t)bb * Sc + row0) * Ec + col] =
            make_float2(o[nf][0] * il0, o[nf][1] * il0);
        *(float2*)&ctx[((size_t)bb * Sc + row0 + 8) * Ec + col] =
            make_float2(o[nf][2] * il1, o[nf][3] * il1);
    }
}

// ---------------- launch ----------------
extern "C" void kernel_launch(void* const* d_in, const int* in_sizes, int n_in,
                              void* d_out, int out_size) {
    const float* x    = (const float*)d_in[0];
    const float* Wq   = (const float*)d_in[2];
    const float* bq   = (const float*)d_in[3];
    const float* Wk   = (const float*)d_in[4];
    const float* bk   = (const float*)d_in[5];
    const float* Wv   = (const float*)d_in[6];
    const float* bv   = (const float*)d_in[7];
    const float* Wo   = (const float*)d_in[8];
    const float* bo   = (const float*)d_in[9];
    const float* W1   = (const float*)d_in[10];
    const float* b1   = (const float*)d_in[11];
    const float* W2   = (const float*)d_in[12];
    const float* b2   = (const float*)d_in[13];
    const float* ln1g = (const float*)d_in[14];
    const float* ln1b = (const float*)d_in[15];
    const float* ln2g = (const float*)d_in[16];
    const float* ln2b = (const float*)d_in[17];
    float* out = (float*)d_out;

    float *n_, *q_, *k_, *v_, *ctx_, *res_, *x2_, *f1_;
    cudaGetSymbolAddress((void**)&n_,   g_n);
    cudaGetSymbolAddress((void**)&q_,   g_q);
    cudaGetSymbolAddress((void**)&k_,   g_k);
    cudaGetSymbolAddress((void**)&v_,   g_v);
    cudaGetSymbolAddress((void**)&ctx_, g_ctx);
    cudaGetSymbolAddress((void**)&res_, g_res);
    cudaGetSymbolAddress((void**)&x2_,  g_x2);
    cudaGetSymbolAddress((void**)&f1_,  g_f1);

    // 1. LN1
    ln_kernel<<<Mc, 256>>>(x, ln1g, ln1b, n_);

    // 2. Q/K/V projections (tf32 TC), written directly in [B,H,S,D]
    tgemm<EP_HEADS><<<dim3(Ec/BN, Mc/BM), 256>>>(n_, Wq, bq, nullptr, q_, Mc, Ec, Ec);
    tgemm<EP_HEADS><<<dim3(Ec/BN, Mc/BM), 256>>>(n_, Wk, bk, nullptr, k_, Mc, Ec, Ec);
    tgemm<EP_HEADS><<<dim3(Ec/BN, Mc/BM), 256>>>(n_, Wv, bv, nullptr, v_, Mc, Ec, Ec);

    // 3. Flash attention (tf32 TC) -> ctx [B,S,E]
    cudaFuncSetAttribute(attn_tc, cudaFuncAttributeMaxDynamicSharedMemorySize, ATTN_SMEM);
    attn_tc<<<dim3(Sc/64, Bc*Hc), 128, ATTN_SMEM>>>(q_, k_, v_, ctx_);

    // 4. Wo projection + residual with x
    tgemm<EP_RES><<<dim3(Ec/BN, Mc/BM), 256>>>(ctx_, Wo, bo, x, res_, Mc, Ec, Ec);

    // 5. LN2
    ln_kernel<<<Mc, 256>>>(res_, ln2g, ln2b, x2_);

    // 6. FFN1 + exact GELU
    tgemm<EP_GELU><<<dim3(Fc/BN, Mc/BM), 256>>>(x2_, W1, b1, nullptr, f1_, Mc, Fc, Ec);

    // 7. FFN2 + bias + residual(x2) -> out
    tgemm<EP_RES><<<dim3(Ec/BN, Mc/BM), 256>>>(f1_, W2, b2, x2_, out, Mc, Ec, Fc);
}

// round 4
// speedup vs baseline: 4.0217x; 1.2993x over previous
#include <cuda_runtime.h>
#include <math.h>
#include <stdint.h>

#define Bc 2
#define Sc 2048
#define Ec 1024
#define Hc 16
#define Dc 64
#define Fc 4096
#define Mc (Bc*Sc)          // 4096 rows

// ---------------- scratch (no cudaMalloc allowed) ----------------
__device__ float g_n  [Mc*Ec];
__device__ float g_q  [Mc*Ec];
__device__ float g_k  [Mc*Ec];
__device__ float g_v  [Mc*Ec];
__device__ float g_ctx[Mc*Ec];
__device__ float g_res[Mc*Ec];
__device__ float g_x2 [Mc*Ec];
__device__ float g_f1 [Mc*Fc];

// ---------------- helpers ----------------
__device__ __forceinline__ void mma8(float* c, const uint32_t* a, const uint32_t* b) {
    asm volatile(
        "mma.sync.aligned.m16n8k8.row.col.f32.tf32.tf32.f32 "
        "{%0,%1,%2,%3}, {%4,%5,%6,%7}, {%8,%9}, {%0,%1,%2,%3};\n"
        : "+f"(c[0]), "+f"(c[1]), "+f"(c[2]), "+f"(c[3])
        : "r"(a[0]), "r"(a[1]), "r"(a[2]), "r"(a[3]),
          "r"(b[0]), "r"(b[1]));
}

__device__ __forceinline__ void cp16(uint32_t dst, const float* src) {
    asm volatile("cp.async.cg.shared.global [%0], [%1], 16;" :: "r"(dst), "l"(src));
}
#define CP_COMMIT() asm volatile("cp.async.commit_group;")
#define CP_WAIT0()  asm volatile("cp.async.wait_group 0;")

// ---------------- LayerNorm ----------------
__global__ void __launch_bounds__(256) ln_kernel(const float* __restrict__ x,
                                                 const float* __restrict__ g,
                                                 const float* __restrict__ b,
                                                 float* __restrict__ out) {
    int row = blockIdx.x;
    int tid = threadIdx.x;
    const float4* xr = (const float4*)(x + (size_t)row * Ec);
    float4 xv = xr[tid];
    float s  = xv.x + xv.y + xv.z + xv.w;
    float sq = xv.x*xv.x + xv.y*xv.y + xv.z*xv.z + xv.w*xv.w;
    #pragma unroll
    for (int o = 16; o; o >>= 1) {
        s  += __shfl_xor_sync(0xffffffffu, s,  o);
        sq += __shfl_xor_sync(0xffffffffu, sq, o);
    }
    __shared__ float ws[8], wq[8];
    __shared__ float s_mu, s_rstd;
    int lane = tid & 31, wid = tid >> 5;
    if (lane == 0) { ws[wid] = s; wq[wid] = sq; }
    __syncthreads();
    if (tid == 0) {
        float S = 0.f, Q = 0.f;
        #pragma unroll
        for (int i = 0; i < 8; i++) { S += ws[i]; Q += wq[i]; }
        float mu  = S * (1.0f / Ec);
        float var = Q * (1.0f / Ec) - mu * mu;
        s_mu = mu;
        s_rstd = rsqrtf(var + 1e-5f);
    }
    __syncthreads();
    float mu = s_mu, rstd = s_rstd;
    float4 gv = ((const float4*)g)[tid];
    float4 bv = ((const float4*)b)[tid];
    float4 ov;
    ov.x = (xv.x - mu) * rstd * gv.x + bv.x;
    ov.y = (xv.y - mu) * rstd * gv.y + bv.y;
    ov.z = (xv.z - mu) * rstd * gv.z + bv.z;
    ov.w = (xv.w - mu) * rstd * gv.w + bv.w;
    ((float4*)(out + (size_t)row * Ec))[tid] = ov;
}

// ---------------- tf32 TC GEMM: 128x128x32, 8 warps, cp.async double buffer ----------------
enum { EP_PLAIN = 0, EP_HEADS = 1, EP_RES = 2, EP_GELU = 3 };

#define BM 128
#define BN 128
#define BK 32
#define LDA 36      // bank = (4m + c) % 32 conflict-free
#define LDB 136     // bank = (8c + n) % 32 conflict-free
#define STG_A (BM * LDA)            // 4608 floats
#define STG_B (BK * LDB)            // 4352 floats
#define STG   (STG_A + STG_B)       // 8960 floats
#define TG_SMEM (2 * STG * 4)       // 71680 bytes

template<int EP>
__global__ void __launch_bounds__(256, 2) tgemm(const float* __restrict__ A,
                                                const float* __restrict__ W,
                                                const float* __restrict__ bias,
                                                const float* __restrict__ res,
                                                float* __restrict__ C,
                                                int M, int N, int K) {
    extern __shared__ float sh[];
    uint32_t smem_u = (uint32_t)__cvta_generic_to_shared(sh);

    int tid  = threadIdx.x;
    int lane = tid & 31;
    int w    = tid >> 5;
    int wm   = (w & 3) * 32;
    int wn   = (w >> 2) * 64;
    int row0 = blockIdx.y * BM;
    int col0 = blockIdx.x * BN;

    const float* Ab = A + (size_t)row0 * K;
    const float* Wb = W + col0;

    int ar  = tid >> 3, akc = (tid & 7) * 4;   // + i*32 rows
    int bkr = tid >> 5, bnc = (tid & 31) * 4;  // + i*8 rows

    // issue copies for k-tile k0 into stage s
    auto issue = [&](int k0, int s) {
        uint32_t sa = smem_u + (uint32_t)(s * STG) * 4u;
        uint32_t sb = sa + (uint32_t)STG_A * 4u;
        #pragma unroll
        for (int i = 0; i < 4; i++) {
            int r = ar + i * 32;
            cp16(sa + (uint32_t)(r * LDA + akc) * 4u, Ab + (size_t)r * K + k0 + akc);
            int kr = bkr + i * 8;
            cp16(sb + (uint32_t)(kr * LDB + bnc) * 4u, Wb + (size_t)(k0 + kr) * N + bnc);
        }
        CP_COMMIT();
    };

    float acc[2][8][4];
    #pragma unroll
    for (int mi = 0; mi < 2; mi++)
        #pragma unroll
        for (int ni = 0; ni < 8; ni++)
            #pragma unroll
            for (int q = 0; q < 4; q++) acc[mi][ni][q] = 0.f;

    int nk = K / BK;
    issue(0, 0);

    int r_ = lane >> 2, c_ = lane & 3;
    for (int kt = 0; kt < nk; kt++) {
        CP_WAIT0();
        __syncthreads();
        if (kt + 1 < nk) issue((kt + 1) * BK, (kt + 1) & 1);

        const uint32_t* Sa = (const uint32_t*)(sh + (kt & 1) * STG);
        const uint32_t* Sb = Sa + STG_A;

        #pragma unroll
        for (int ks = 0; ks < 4; ks++) {
            int kb = ks * 8;
            uint32_t af[2][4], bf[8][2];
            #pragma unroll
            for (int mi = 0; mi < 2; mi++) {
                int m = wm + mi * 16 + r_;
                af[mi][0] = Sa[m * LDA + kb + c_];
                af[mi][1] = Sa[(m + 8) * LDA + kb + c_];
                af[mi][2] = Sa[m * LDA + kb + c_ + 4];
                af[mi][3] = Sa[(m + 8) * LDA + kb + c_ + 4];
            }
            #pragma unroll
            for (int ni = 0; ni < 8; ni++) {
                int n = wn + ni * 8 + r_;
                bf[ni][0] = Sb[(kb + c_) * LDB + n];
                bf[ni][1] = Sb[(kb + c_ + 4) * LDB + n];
            }
            #pragma unroll
            for (int mi = 0; mi < 2; mi++)
                #pragma unroll
                for (int ni = 0; ni < 8; ni++)
                    mma8(acc[mi][ni], af[mi], bf[ni]);
        }
        __syncthreads();
    }

    // ---- epilogue ----
    int c2 = (lane & 3) * 2;
    #pragma unroll
    for (int mi = 0; mi < 2; mi++) {
        #pragma unroll
        for (int ni = 0; ni < 8; ni++) {
            #pragma unroll
            for (int h = 0; h < 2; h++) {
                int row = row0 + wm + mi * 16 + r_ + h * 8;
                int col = col0 + wn + ni * 8 + c2;
                float v0 = acc[mi][ni][h * 2 + 0] + bias[col];
                float v1 = acc[mi][ni][h * 2 + 1] + bias[col + 1];
                if (EP == EP_GELU) {
                    v0 = 0.5f * v0 * (1.f + erff(v0 * 0.70710678118654752f));
                    v1 = 0.5f * v1 * (1.f + erff(v1 * 0.70710678118654752f));
                }
                if (EP == EP_RES) {
                    v0 += res[(size_t)row * N + col];
                    v1 += res[(size_t)row * N + col + 1];
                }
                if (EP == EP_HEADS) {
                    int bb = row >> 11, ss = row & 2047;
                    int hh = col >> 6,  dd = col & 63;
                    *(float2*)&C[(((size_t)(bb * Hc + hh)) * Sc + ss) * Dc + dd] =
                        make_float2(v0, v1);
                } else {
                    *(float2*)&C[(size_t)row * N + col] = make_float2(v0, v1);
                }
            }
        }
    }
}

// ---------------- tf32 TC flash attention ----------------
#define LDK 68
#define LDV 72
#define LDP 68
#define ATTN_SMEM ((64*LDK + 64*LDV + 64*LDP) * 4)

__global__ void __launch_bounds__(128) attn_tc(const float* __restrict__ Q,
                                               const float* __restrict__ K,
                                               const float* __restrict__ V,
                                               float* __restrict__ ctx) {
    extern __shared__ uint32_t smu[];
    uint32_t* Ks = smu;
    uint32_t* Vs = Ks + 64 * LDK;
    uint32_t* Ps = Vs + 64 * LDV;

    int tid = threadIdx.x, lane = tid & 31, w = tid >> 5;
    int r_ = lane >> 2, c_ = lane & 3;
    int qt = (int)gridDim.x - 1 - (int)blockIdx.x;
    int bh = blockIdx.y;
    int q0 = qt * 64;

    const float* Qb = Q + (size_t)bh * Sc * Dc;
    const float* Kb = K + (size_t)bh * Sc * Dc;
    const float* Vb = V + (size_t)bh * Sc * Dc;

    #pragma unroll
    for (int it = 0; it < 8; it++) {
        int idx = tid + it * 128;
        int r = idx >> 4, d4 = (idx & 15) * 4;
        float4 f = *(const float4*)(Qb + (size_t)(q0 + r) * Dc + d4);
        Ps[r * LDP + d4 + 0] = __float_as_uint(f.x * 0.125f);
        Ps[r * LDP + d4 + 1] = __float_as_uint(f.y * 0.125f);
        Ps[r * LDP + d4 + 2] = __float_as_uint(f.z * 0.125f);
        Ps[r * LDP + d4 + 3] = __float_as_uint(f.w * 0.125f);
    }
    __syncthreads();
    uint32_t qf[8][4];
    {
        const uint32_t* pw0 = Ps + w * 16 * LDP;
        #pragma unroll
        for (int kc = 0; kc < 8; kc++) {
            int kb = kc * 8;
            qf[kc][0] = pw0[r_ * LDP + kb + c_];
            qf[kc][1] = pw0[(r_ + 8) * LDP + kb + c_];
            qf[kc][2] = pw0[r_ * LDP + kb + c_ + 4];
            qf[kc][3] = pw0[(r_ + 8) * LDP + kb + c_ + 4];
        }
    }

    float o[8][4];
    #pragma unroll
    for (int nf = 0; nf < 8; nf++)
        #pragma unroll
        for (int q = 0; q < 4; q++) o[nf][q] = 0.f;
    float m0 = -1e30f, m1 = -1e30f, l0 = 0.f, l1 = 0.f;

    uint32_t* pw = Ps + w * 16 * LDP;

    for (int kt = 0; kt <= qt; kt++) {
        int k0 = kt * 64;
        __syncthreads();
        #pragma unroll
        for (int it = 0; it < 8; it++) {
            int idx = tid + it * 128;
            int r = idx >> 4, d4 = (idx & 15) * 4;
            float4 fk = *(const float4*)(Kb + (size_t)(k0 + r) * Dc + d4);
            Ks[r * LDK + d4 + 0] = __float_as_uint(fk.x);
            Ks[r * LDK + d4 + 1] = __float_as_uint(fk.y);
            Ks[r * LDK + d4 + 2] = __float_as_uint(fk.z);
            Ks[r * LDK + d4 + 3] = __float_as_uint(fk.w);
            float4 fv = *(const float4*)(Vb + (size_t)(k0 + r) * Dc + d4);
            Vs[r * LDV + d4 + 0] = __float_as_uint(fv.x);
            Vs[r * LDV + d4 + 1] = __float_as_uint(fv.y);
            Vs[r * LDV + d4 + 2] = __float_as_uint(fv.z);
            Vs[r * LDV + d4 + 3] = __float_as_uint(fv.w);
        }
        __syncthreads();

        float sacc[8][4];
        #pragma unroll
        for (int nf = 0; nf < 8; nf++)
            #pragma unroll
            for (int q = 0; q < 4; q++) sacc[nf][q] = 0.f;
        #pragma unroll
        for (int kc = 0; kc < 8; kc++) {
            int kb = kc * 8;
            #pragma unroll
            for (int nf = 0; nf < 8; nf++) {
                uint32_t b[2];
                b[0] = Ks[(nf * 8 + r_) * LDK + kb + c_];
                b[1] = Ks[(nf * 8 + r_) * LDK + kb + c_ + 4];
                mma8(sacc[nf], qf[kc], b);
            }
        }

        if (kt == qt) {
            int rr = w * 16 + r_;
            #pragma unroll
            for (int nf = 0; nf < 8; nf++) {
                int cb = nf * 8 + 2 * c_;
                if (cb     > rr)     sacc[nf][0] = -1e30f;
                if (cb + 1 > rr)     sacc[nf][1] = -1e30f;
                if (cb     > rr + 8) sacc[nf][2] = -1e30f;
                if (cb + 1 > rr + 8) sacc[nf][3] = -1e30f;
            }
        }

        float mx0 = -1e30f, mx1 = -1e30f;
        #pragma unroll
        for (int nf = 0; nf < 8; nf++) {
            mx0 = fmaxf(mx0, fmaxf(sacc[nf][0], sacc[nf][1]));
            mx1 = fmaxf(mx1, fmaxf(sacc[nf][2], sacc[nf][3]));
        }
        mx0 = fmaxf(mx0, __shfl_xor_sync(0xffffffffu, mx0, 1));
        mx0 = fmaxf(mx0, __shfl_xor_sync(0xffffffffu, mx0, 2));
        mx1 = fmaxf(mx1, __shfl_xor_sync(0xffffffffu, mx1, 1));
        mx1 = fmaxf(mx1, __shfl_xor_sync(0xffffffffu, mx1, 2));
        float mn0 = fmaxf(m0, mx0), mn1 = fmaxf(m1, mx1);
        float es0 = __expf(m0 - mn0), es1 = __expf(m1 - mn1);
        m0 = mn0; m1 = mn1;
        float ls0 = 0.f, ls1 = 0.f;
        #pragma unroll
        for (int nf = 0; nf < 8; nf++) {
            sacc[nf][0] = __expf(sacc[nf][0] - mn0);
            sacc[nf][1] = __expf(sacc[nf][1] - mn0);
            sacc[nf][2] = __expf(sacc[nf][2] - mn1);
            sacc[nf][3] = __expf(sacc[nf][3] - mn1);
            ls0 += sacc[nf][0] + sacc[nf][1];
            ls1 += sacc[nf][2] + sacc[nf][3];
        }
        ls0 += __shfl_xor_sync(0xffffffffu, ls0, 1);
        ls0 += __shfl_xor_sync(0xffffffffu, ls0, 2);
        ls1 += __shfl_xor_sync(0xffffffffu, ls1, 1);
        ls1 += __shfl_xor_sync(0xffffffffu, ls1, 2);
        l0 = l0 * es0 + ls0;
        l1 = l1 * es1 + ls1;
        #pragma unroll
        for (int nf = 0; nf < 8; nf++) {
            o[nf][0] *= es0; o[nf][1] *= es0;
            o[nf][2] *= es1; o[nf][3] *= es1;
        }

        #pragma unroll
        for (int nf = 0; nf < 8; nf++) {
            int cb = nf * 8 + 2 * c_;
            pw[r_ * LDP + cb]           = __float_as_uint(sacc[nf][0]);
            pw[r_ * LDP + cb + 1]       = __float_as_uint(sacc[nf][1]);
            pw[(r_ + 8) * LDP + cb]     = __float_as_uint(sacc[nf][2]);
            pw[(r_ + 8) * LDP + cb + 1] = __float_as_uint(sacc[nf][3]);
        }
        __syncwarp();

        #pragma unroll
        for (int kc = 0; kc < 8; kc++) {
            int kb = kc * 8;
            uint32_t af[4];
            af[0] = pw[r_ * LDP + kb + c_];
            af[1] = pw[(r_ + 8) * LDP + kb + c_];
            af[2] = pw[r_ * LDP + kb + c_ + 4];
            af[3] = pw[(r_ + 8) * LDP + kb + c_ + 4];
            #pragma unroll
            for (int nf = 0; nf < 8; nf++) {
                uint32_t b[2];
                b[0] = Vs[(kb + c_) * LDV + nf * 8 + r_];
                b[1] = Vs[(kb + c_ + 4) * LDV + nf * 8 + r_];
                mma8(o[nf], af, b);
            }
        }
        __syncwarp();
    }

    int bb = bh >> 4, hh = bh & 15;
    int row0 = q0 + w * 16 + r_;
    float il0 = 1.f / l0, il1 = 1.f / l1;
    #pragma unroll
    for (int nf = 0; nf < 8; nf++) {
        int col = hh * 64 + nf * 8 + 2 * c_;
        *(float2*)&ctx[((size_t)bb * Sc + row0) * Ec + col] =
            make_float2(o[nf][0] * il0, o[nf][1] * il0);
        *(float2*)&ctx[((size_t)bb * Sc + row0 + 8) * Ec + col] =
            make_float2(o[nf][2] * il1, o[nf][3] * il1);
    }
}

// ---------------- launch ----------------
extern "C" void kernel_launch(void* const* d_in, const int* in_sizes, int n_in,
                              void* d_out, int out_size) {
    const float* x    = (const float*)d_in[0];
    const float* Wq   = (const float*)d_in[2];
    const float* bq   = (const float*)d_in[3];
    const float* Wk   = (const float*)d_in[4];
    const float* bk   = (const float*)d_in[5];
    const float* Wv   = (const float*)d_in[6];
    const float* bv   = (const float*)d_in[7];
    const float* Wo   = (const float*)d_in[8];
    const float* bo   = (const float*)d_in[9];
    const float* W1   = (const float*)d_in[10];
    const float* b1   = (const float*)d_in[11];
    const float* W2   = (const float*)d_in[12];
    const float* b2   = (const float*)d_in[13];
    const float* ln1g = (const float*)d_in[14];
    const float* ln1b = (const float*)d_in[15];
    const float* ln2g = (const float*)d_in[16];
    const float* ln2b = (const float*)d_in[17];
    float* out = (float*)d_out;

    float *n_, *q_, *k_, *v_, *ctx_, *res_, *x2_, *f1_;
    cudaGetSymbolAddress((void**)&n_,   g_n);
    cudaGetSymbolAddress((void**)&q_,   g_q);
    cudaGetSymbolAddress((void**)&k_,   g_k);
    cudaGetSymbolAddress((void**)&v_,   g_v);
    cudaGetSymbolAddress((void**)&ctx_, g_ctx);
    cudaGetSymbolAddress((void**)&res_, g_res);
    cudaGetSymbolAddress((void**)&x2_,  g_x2);
    cudaGetSymbolAddress((void**)&f1_,  g_f1);

    cudaFuncSetAttribute(tgemm<EP_HEADS>, cudaFuncAttributeMaxDynamicSharedMemorySize, TG_SMEM);
    cudaFuncSetAttribute(tgemm<EP_RES>,   cudaFuncAttributeMaxDynamicSharedMemorySize, TG_SMEM);
    cudaFuncSetAttribute(tgemm<EP_GELU>,  cudaFuncAttributeMaxDynamicSharedMemorySize, TG_SMEM);
    cudaFuncSetAttribute(attn_tc, cudaFuncAttributeMaxDynamicSharedMemorySize, ATTN_SMEM);

    // 1. LN1
    ln_kernel<<<Mc, 256>>>(x, ln1g, ln1b, n_);

    // 2. Q/K/V projections (tf32 TC), written directly in [B,H,S,D]
    tgemm<EP_HEADS><<<dim3(Ec/BN, Mc/BM), 256, TG_SMEM>>>(n_, Wq, bq, nullptr, q_, Mc, Ec, Ec);
    tgemm<EP_HEADS><<<dim3(Ec/BN, Mc/BM), 256, TG_SMEM>>>(n_, Wk, bk, nullptr, k_, Mc, Ec, Ec);
    tgemm<EP_HEADS><<<dim3(Ec/BN, Mc/BM), 256, TG_SMEM>>>(n_, Wv, bv, nullptr, v_, Mc, Ec, Ec);

    // 3. Flash attention (tf32 TC) -> ctx [B,S,E]
    attn_tc<<<dim3(Sc/64, Bc*Hc), 128, ATTN_SMEM>>>(q_, k_, v_, ctx_);

    // 4. Wo projection + residual with x
    tgemm<EP_RES><<<dim3(Ec/BN, Mc/BM), 256, TG_SMEM>>>(ctx_, Wo, bo, x, res_, Mc, Ec, Ec);

    // 5. LN2
    ln_kernel<<<Mc, 256>>>(res_, ln2g, ln2b, x2_);

    // 6. FFN1 + exact GELU
    tgemm<EP_GELU><<<dim3(Fc/BN, Mc/BM), 256, TG_SMEM>>>(x2_, W1, b1, nullptr, f1_, Mc, Fc, Ec);

    // 7. FFN2 + bias + residual(x2) -> out
    tgemm<EP_RES><<<dim3(Ec/BN, Mc/BM), 256, TG_SMEM>>>(f1_, W2, b2, x2_, out, Mc, Ec, Fc);
}